// round 16
// baseline (speedup 1.0000x reference)
#include <cuda_runtime.h>
#include <cuda_fp16.h>
#include <cstdint>

// Problem constants
#define BN   8
#define CN   256
#define HN   64
#define WN   64
#define GN   4
#define KKN  9
#define CG   64
#define OCF  108
#define HWN  (HN*WN)

// ---------------------------------------------------------------------------
// Scratch
// ---------------------------------------------------------------------------
__device__ float    g_off [BN*OCF*HWN];        // offset/mask conv output
__device__ float    g_out [BN*CN*HWN];         // DCN conv output (pre-LN)
__device__ uint32_t g_wT_h[GN*KKN*2048];       // w_dcn fp16 fragment-baked (m16n8k16)
__device__ uint32_t g_wA_h[8*KKN*2048];        // w_off fp16 fragment-baked
__device__ uint4    g_xH  [BN*GN*8*HWN];       // x fp16 8-ch interleave: [b][g][c8][px]

// ---------------------------------------------------------------------------
// helpers
// ---------------------------------------------------------------------------
__device__ __forceinline__ void mma_f16(float* d, uint32_t a0, uint32_t a1,
                                        uint32_t a2, uint32_t a3,
                                        uint32_t b0, uint32_t b1) {
    asm volatile(
        "mma.sync.aligned.m16n8k16.row.col.f32.f16.f16.f32 "
        "{%0,%1,%2,%3}, {%4,%5,%6,%7}, {%8,%9}, {%0,%1,%2,%3};"
        : "+f"(d[0]), "+f"(d[1]), "+f"(d[2]), "+f"(d[3])
        : "r"(a0), "r"(a1), "r"(a2), "r"(a3), "r"(b0), "r"(b1));
}
__device__ __forceinline__ uint32_t pack_h2(float a, float b) {
    __half2 h = __floats2half2_rn(a, b);      // .x (low) = a
    return *reinterpret_cast<uint32_t*>(&h);
}
__device__ __forceinline__ __half2 u2h(uint32_t u) {
    return *reinterpret_cast<__half2*>(&u);
}
__device__ __forceinline__ uint32_t h2u(__half2 h) {
    return *reinterpret_cast<uint32_t*>(&h);
}

// ---------------------------------------------------------------------------
// Kernel 0a: w_dcn -> g_wT_h fp16 fragment-baked (m16n8k16).
// ---------------------------------------------------------------------------
__global__ void __launch_bounds__(256) prep_wT_k(const float* __restrict__ w_dcn)
{
    int i = blockIdx.x * 256 + threadIdx.x;
    if (i >= GN*KKN*2048) return;
    int tile = i >> 11;
    int j    = i & 2047;
    int r    = j & 3;
    int lane = (j >> 2) & 31;
    int fs   = j >> 7;                 // 0..15 = mt*4 + step
    int mt   = fs >> 2, step = fs & 3;
    int k    = tile % 9;
    int g    = tile / 9;
    int oc   = mt*16 + ((r & 1) << 3) + (lane >> 2);
    int c0   = step*16 + ((lane & 3) << 1) + ((r >> 1) << 3);
    float w0 = w_dcn[((g*CG + oc)*CG + c0    )*KKN + k];
    float w1 = w_dcn[((g*CG + oc)*CG + c0 + 1)*KKN + k];
    g_wT_h[i] = pack_h2(w0, w1);
}

// ---------------------------------------------------------------------------
// Kernel 0b: w_off -> g_wA_h fp16 fragment-baked.
// ---------------------------------------------------------------------------
__global__ void __launch_bounds__(256) prep_wA_k(const float* __restrict__ w_off)
{
    int i = blockIdx.x * 256 + threadIdx.x;
    if (i >= 8*KKN*2048) return;
    int tile = i >> 11;
    int j    = i & 2047;
    int r    = j & 3;
    int lane = (j >> 2) & 31;
    int fs   = j >> 7;                 // 0..15 = mt*2 + step
    int mt   = fs >> 1, step = fs & 1;
    int kk   = tile % 9;
    int cc   = tile / 9;
    int oc   = mt*16 + ((r & 1) << 3) + (lane >> 2);
    int c0   = step*16 + ((lane & 3) << 1) + ((r >> 1) << 3);
    float w0 = 0.f, w1 = 0.f;
    if (oc < OCF) {
        w0 = w_off[(oc*CN + cc*32 + c0    )*KKN + kk];
        w1 = w_off[(oc*CN + cc*32 + c0 + 1)*KKN + kk];
    }
    g_wA_h[i] = pack_h2(w0, w1);
}

// ---------------------------------------------------------------------------
// Kernel 0c: build g_xH[b][g][c8][px] (8 fp16 channels per uint4).
// ---------------------------------------------------------------------------
__global__ void __launch_bounds__(256) build_xH_k(const float* __restrict__ x)
{
    const int bg = blockIdx.z;
    const int c8 = blockIdx.y;
    const int px = blockIdx.x * 256 + threadIdx.x;
    const float* src = x + (size_t)bg*CG*HWN + c8*8*HWN + px;
    uint4 o;
    o.x = pack_h2(src[0],     src[HWN]);
    o.y = pack_h2(src[2*HWN], src[3*HWN]);
    o.z = pack_h2(src[4*HWN], src[5*HWN]);
    o.w = pack_h2(src[6*HWN], src[7*HWN]);
    g_xH[(size_t)(bg*8 + c8)*HWN + px] = o;
}

// ---------------------------------------------------------------------------
// Kernel 1: offset/mask conv, fp16 m16n8k16. 1 h-row per block, 32 acc/thr.
// grid (HN, BN) = 512 blocks, block 256 (8 warps), 3 CTAs/SM target.
// Warp tile 32oc x 32px: mg = wid&3, ch = wid>>2 (px half).
// Patch: 3 rows (h-1..h+1) x 16 crow x 72 half2; zeroed once.
// ---------------------------------------------------------------------------
#define OFC_BYTES (3*16*72*4)

__global__ void __launch_bounds__(256, 3) offset_conv_mma_k(
    const float* __restrict__ x, const float* __restrict__ b_off)
{
    extern __shared__ char smc[];
    uint32_t* patch_u = (uint32_t*)smc;
    const uint32_t* PH = (const uint32_t*)smc;

    const int h   = blockIdx.x;
    const int b   = blockIdx.y;
    const int t   = threadIdx.x;
    const int wid = t >> 5;
    const int lane = t & 31;
    const int lm4 = lane & 3;
    const int ld4 = lane >> 2;
    const int mg  = wid & 3;
    const int ch  = wid >> 2;         // px half: ch*32

    float D[2][4][4];
#pragma unroll
    for (int s = 0; s < 2; s++)
#pragma unroll
        for (int n = 0; n < 4; n++)
#pragma unroll
            for (int i = 0; i < 4; i++) D[s][n][i] = 0.f;

    // one-time zero (halo cols + out-of-range rows stay zero)
#pragma unroll
    for (int i = t; i < 3*16*72; i += 256) patch_u[i] = 0u;

    const int colT = t & 63;
    const int p0   = t >> 6;          // 0..3

    for (int cc = 0; cc < 8; cc++) {
        __syncthreads();
        {
            const float* xb = x + ((b*CN + cc*32)*HN)*WN + colT;
#pragma unroll
            for (int p = p0; p < 48; p += 4) {
                int crow = p & 15;
                int r    = p >> 4;    // 0..2
                int y    = h - 1 + r;
                float v0 = 0.f, v1 = 0.f;
                if ((unsigned)y < HN) {
                    const float* xp = xb + (2*crow*HN + y)*WN;
                    v0 = xp[0];
                    v1 = xp[HWN];
                }
                patch_u[(r*16 + crow)*72 + colT + 1] = pack_h2(v0, v1);
            }
        }
        __syncthreads();

        for (int kk = 0; kk < KKN; kk++) {
            const uint4* wf = (const uint4*)(g_wA_h + (cc*9 + kk)*2048);
            const int ky = kk / 3, kx = kk - (kk/3)*3;
#pragma unroll
            for (int st = 0; st < 2; st++) {
                uint4 af0 = wf[((mg*2 + 0)*2 + st)*32 + lane];
                uint4 af1 = wf[((mg*2 + 1)*2 + st)*32 + lane];
                const int bb = (ky*16 + st*8 + lm4)*72 + kx + ch*32 + ld4;
#pragma unroll
                for (int nt = 0; nt < 4; nt++) {
                    uint32_t b0 = PH[bb + nt*8];
                    uint32_t b1 = PH[bb + 4*72 + nt*8];
                    mma_f16(D[0][nt], af0.x, af0.y, af0.z, af0.w, b0, b1);
                    mma_f16(D[1][nt], af1.x, af1.y, af1.z, af1.w, b0, b1);
                }
            }
        }
    }

#pragma unroll
    for (int s = 0; s < 2; s++) {
#pragma unroll
        for (int nt = 0; nt < 4; nt++) {
            int ocA = mg*32 + s*16 + ld4;
            int ocB = ocA + 8;
            int w   = ch*32 + nt*8 + lm4*2;
            if (ocA < OCF) {
                float bo = b_off[ocA];
                *reinterpret_cast<float2*>(&g_off[((b*OCF + ocA)*HN + h)*WN + w])
                    = make_float2(D[s][nt][0] + bo, D[s][nt][1] + bo);
            }
            if (ocB < OCF) {
                float bo = b_off[ocB];
                *reinterpret_cast<float2*>(&g_off[((b*OCF + ocB)*HN + h)*WN + w])
                    = make_float2(D[s][nt][2] + bo, D[s][nt][3] + bo);
            }
        }
    }
}

// ---------------------------------------------------------------------------
// Kernel 2: deformable sampling + grouped conv, fp16 m16n8k16.
// 2 h-rows per block (128 px), 32 acc/thr, 3 CTAs/SM target.
// grid (HN/2, GN, BN) = 1024 blocks, block 256 (8 warps).
// Warp tile 32oc x 32px: mg = wid&1, ng = wid>>1 (px chunk ng*32).
// Gather: 2 threads/pixel, each 4 c8-chunks. S: [32 crow][136 px] half2.
// ---------------------------------------------------------------------------
#define DCN_PITCH  136
#define DCN_BYTES  (32*DCN_PITCH*4)

__global__ void __launch_bounds__(256, 3) dcn_mma_k(
    const float* __restrict__ b_dcn)
{
    extern __shared__ char smc[];
    uint32_t* SH = (uint32_t*)smc;    // half2 units

    const int h0 = blockIdx.x * 2;
    const int g  = blockIdx.y;
    const int b  = blockIdx.z;
    const int t  = threadIdx.x;
    const int wid = t >> 5;
    const int lane = t & 31;
    const int lm4 = lane & 3;
    const int ld4 = lane >> 2;
    const int mg  = wid & 1;          // oc half: mg*32
    const int ng  = wid >> 1;         // px chunk: ng*32

    const int pxA   = t & 127;        // pixel (2 threads per pixel)
    const int chalf = t >> 7;         // c8 chunk half
    const int hA  = h0 + (pxA >> 6);
    const int wA  = pxA & 63;
    const uint4* xh = g_xH + (size_t)(b*GN + g)*8*HWN;

    float D[2][4][4];
#pragma unroll
    for (int s = 0; s < 2; s++)
#pragma unroll
        for (int n = 0; n < 4; n++)
#pragma unroll
            for (int i = 0; i < 4; i++) D[s][n][i] = 0.f;

    for (int k = 0; k < KKN; k++) {
        __syncthreads();   // previous mma done reading S
        // ---- bilinear corner data (registers; duplicated per pixel-pair) ----
        int i0, i1, i2, i3;
        __half2 w0h, w1h, w2h, w3h;
        {
            int ky = k / 3 - 1;
            int kx = k - (k/3)*3 - 1;
            int sp = hA*WN + wA;
            const float* ob = g_off + b*OCF*HWN;
            float oy = ob[((g*KKN + k)*2    )*HWN + sp];
            float ox = ob[((g*KKN + k)*2 + 1)*HWN + sp];
            float mz = ob[(2*GN*KKN + g*KKN + k)*HWN + sp];
            float mk = 1.f / (1.f + expf(-mz));
            float py  = (float)(hA + ky) + oy;
            float pxx = (float)(wA + kx) + ox;
            float y0f = floorf(py),  x0f = floorf(pxx);
            float wy1 = py - y0f,    wx1 = pxx - x0f;
            float wy0 = 1.f - wy1,   wx0 = 1.f - wx1;
            int y0 = (int)y0f, x0i = (int)x0f;
            int y1 = y0 + 1,   x1i = x0i + 1;
            bool vy0 = (y0 >= 0) & (y0 < HN);
            bool vy1 = (y1 >= 0) & (y1 < HN);
            bool vx0 = (x0i >= 0) & (x0i < WN);
            bool vx1 = (x1i >= 0) & (x1i < WN);
            int y0c = min(max(y0, 0), HN-1), y1c = min(max(y1, 0), HN-1);
            int x0c = min(max(x0i,0), WN-1), x1c = min(max(x1i,0), WN-1);
            i0 = y0c*WN + x0c;  i1 = y0c*WN + x1c;
            i2 = y1c*WN + x0c;  i3 = y1c*WN + x1c;
            w0h = __float2half2_rn((vy0 && vx0) ? wy0*wx0*mk : 0.f);
            w1h = __float2half2_rn((vy0 && vx1) ? wy0*wx1*mk : 0.f);
            w2h = __float2half2_rn((vy1 && vx0) ? wy1*wx0*mk : 0.f);
            w3h = __float2half2_rn((vy1 && vx1) ? wy1*wx1*mk : 0.f);
        }
        // ---- gather: 4 c8-chunks (chalf*4..+3); HFMA2 interpolation ----
#pragma unroll
        for (int cc8 = 0; cc8 < 4; cc8++) {
            const int c8 = chalf*4 + cc8;
            const uint4* pl = xh + (size_t)c8*HWN;
            uint4 A = pl[i0], Bv = pl[i1], Cv = pl[i2], Dv = pl[i3];
            uint32_t* srow = SH + (4*c8)*DCN_PITCH + pxA;
            __half2 r;
            r = __hmul2(u2h(A.x), w0h);
            r = __hfma2(u2h(Bv.x), w1h, r);
            r = __hfma2(u2h(Cv.x), w2h, r);
            r = __hfma2(u2h(Dv.x), w3h, r);
            srow[0] = h2u(r);
            r = __hmul2(u2h(A.y), w0h);
            r = __hfma2(u2h(Bv.y), w1h, r);
            r = __hfma2(u2h(Cv.y), w2h, r);
            r = __hfma2(u2h(Dv.y), w3h, r);
            srow[DCN_PITCH] = h2u(r);
            r = __hmul2(u2h(A.z), w0h);
            r = __hfma2(u2h(Bv.z), w1h, r);
            r = __hfma2(u2h(Cv.z), w2h, r);
            r = __hfma2(u2h(Dv.z), w3h, r);
            srow[2*DCN_PITCH] = h2u(r);
            r = __hmul2(u2h(A.w), w0h);
            r = __hfma2(u2h(Bv.w), w1h, r);
            r = __hfma2(u2h(Cv.w), w2h, r);
            r = __hfma2(u2h(Dv.w), w3h, r);
            srow[3*DCN_PITCH] = h2u(r);
        }
        __syncthreads();

        // ---- mma: K=64 -> 4 k16-steps; A frags LDG.128, B frags LDS.32 ----
        const uint4* wf = (const uint4*)(g_wT_h + (g*KKN + k)*2048);
        const int nb = ng*32 + ld4;
#pragma unroll
        for (int st = 0; st < 4; st++) {
            uint4 af0 = wf[((mg*2 + 0)*4 + st)*32 + lane];
            uint4 af1 = wf[((mg*2 + 1)*4 + st)*32 + lane];
            const int bb = (st*8 + lm4)*DCN_PITCH + nb;
#pragma unroll
            for (int nt = 0; nt < 4; nt++) {
                uint32_t b0 = SH[bb + nt*8];
                uint32_t b1 = SH[bb + 4*DCN_PITCH + nt*8];
                mma_f16(D[0][nt], af0.x, af0.y, af0.z, af0.w, b0, b1);
                mma_f16(D[1][nt], af1.x, af1.y, af1.z, af1.w, b0, b1);
            }
        }
    }

    // ---- epilogue: +bias, store ----
    const int h = h0 + (ng >> 1);
#pragma unroll
    for (int s = 0; s < 2; s++) {
#pragma unroll
        for (int nt = 0; nt < 4; nt++) {
            int ocA = g*CG + mg*32 + s*16 + ld4;
            int ocB = ocA + 8;
            int w   = (ng & 1)*32 + nt*8 + lm4*2;
            float boA = b_dcn[ocA], boB = b_dcn[ocB];
            *reinterpret_cast<float2*>(&g_out[((b*CN + ocA)*HN + h)*WN + w])
                = make_float2(D[s][nt][0] + boA, D[s][nt][1] + boA);
            *reinterpret_cast<float2*>(&g_out[((b*CN + ocB)*HN + h)*WN + w])
                = make_float2(D[s][nt][2] + boB, D[s][nt][3] + boB);
        }
    }
}

// ---------------------------------------------------------------------------
// Kernel 3: LayerNorm over C + sigmoid + gate — float4 I/O, register values.
// grid (HN, BN), block 256. Thread: 4-px quad (q=t&15) x 16 ch (cp=t>>4).
// ---------------------------------------------------------------------------
__global__ void __launch_bounds__(256) ln_gate_k(
    const float* __restrict__ x, const float* __restrict__ gamma,
    const float* __restrict__ beta, float* __restrict__ out)
{
    __shared__ float4 ssum[16][16];   // [cp][q]
    __shared__ float4 ssq [16][16];
    __shared__ float  smu[64], srinv[64];
    __shared__ float  sg[CN], sb[CN];

    const int b = blockIdx.y;
    const int h = blockIdx.x;
    const int t = threadIdx.x;
    const int q  = t & 15;
    const int cp = t >> 4;
    const int base = b*CN*HWN + h*WN;

    if (t < CN) { sg[t] = gamma[t]; sb[t] = beta[t]; }

    const float4* src = (const float4*)(g_out + base);
    float4 v[16];
    float4 s  = make_float4(0.f, 0.f, 0.f, 0.f);
    float4 qq = make_float4(0.f, 0.f, 0.f, 0.f);
#pragma unroll
    for (int j = 0; j < 16; j++) {
        float4 vv = src[(cp*16 + j)*(HWN/4) + q];
        v[j] = vv;
        s.x += vv.x; s.y += vv.y; s.z += vv.z; s.w += vv.w;
        qq.x += vv.x*vv.x; qq.y += vv.y*vv.y; qq.z += vv.z*vv.z; qq.w += vv.w*vv.w;
    }
    ssum[cp][q] = s; ssq[cp][q] = qq;
    __syncthreads();
    if (t < 64) {
        int pq = t >> 2, cm = t & 3;
        float ss = 0.f, sq = 0.f;
#pragma unroll
        for (int c2 = 0; c2 < 16; c2++) {
            ss += (&ssum[c2][pq].x)[cm];
            sq += (&ssq [c2][pq].x)[cm];
        }
        float mu  = ss * (1.f/CN);
        float var = fmaxf(sq * (1.f/CN) - mu*mu, 0.f);
        smu[t]   = mu;
        srinv[t] = rsqrtf(var + 1e-5f);
    }
    __syncthreads();

    const float4 mu4 = *reinterpret_cast<const float4*>(&smu[q*4]);
    const float4 ri4 = *reinterpret_cast<const float4*>(&srinv[q*4]);
    const float4* xs = (const float4*)(x + base);
    float4* os = (float4*)(out + base);
#pragma unroll
    for (int j = 0; j < 16; j++) {
        int c = cp*16 + j;
        float gm = sg[c], bt = sb[c];
        float4 xv = xs[c*(HWN/4) + q];
        float4 o;
        float z;
        z = (v[j].x - mu4.x) * ri4.x * gm + bt; o.x = xv.x / (1.f + expf(-z));
        z = (v[j].y - mu4.y) * ri4.y * gm + bt; o.y = xv.y / (1.f + expf(-z));
        z = (v[j].z - mu4.z) * ri4.z * gm + bt; o.z = xv.z / (1.f + expf(-z));
        z = (v[j].w - mu4.w) * ri4.w * gm + bt; o.w = xv.w / (1.f + expf(-z));
        os[c*(HWN/4) + q] = o;
    }
}

// ---------------------------------------------------------------------------
// Entry point
// ---------------------------------------------------------------------------
extern "C" void kernel_launch(void* const* d_in, const int* in_sizes, int n_in,
                              void* d_out, int out_size)
{
    const float* x     = (const float*)d_in[0];
    const float* w_off = (const float*)d_in[1];
    const float* b_off = (const float*)d_in[2];
    const float* w_dcn = (const float*)d_in[3];
    const float* b_dcn = (const float*)d_in[4];
    const float* gamma = (const float*)d_in[5];
    const float* beta  = (const float*)d_in[6];
    float* out = (float*)d_out;

    (void)in_sizes; (void)n_in; (void)out_size;

    cudaFuncSetAttribute(offset_conv_mma_k, cudaFuncAttributeMaxDynamicSharedMemorySize,
                         OFC_BYTES);
    cudaFuncSetAttribute(dcn_mma_k, cudaFuncAttributeMaxDynamicSharedMemorySize,
                         DCN_BYTES);

    prep_wT_k<<<(GN*KKN*2048 + 255)/256, 256>>>(w_dcn);
    prep_wA_k<<<(8*KKN*2048 + 255)/256, 256>>>(w_off);
    build_xH_k<<<dim3(HWN/256, 8, BN*GN), 256>>>(x);
    offset_conv_mma_k<<<dim3(HN, BN), 256, OFC_BYTES>>>(x, b_off);
    dcn_mma_k<<<dim3(HN/2, GN, BN), 256, DCN_BYTES>>>(b_dcn);
    ln_gate_k<<<dim3(HN, BN), 256>>>(x, gamma, beta, out);
}

// round 17
// speedup vs baseline: 1.0813x; 1.0813x over previous
#include <cuda_runtime.h>
#include <cuda_fp16.h>
#include <cstdint>

// Problem constants
#define BN   8
#define CN   256
#define HN   64
#define WN   64
#define GN   4
#define KKN  9
#define CG   64
#define OCF  108
#define HWN  (HN*WN)

// ---------------------------------------------------------------------------
// Scratch
// ---------------------------------------------------------------------------
__device__ float    g_off [BN*OCF*HWN];        // offset/mask conv output
__device__ float    g_out [BN*CN*HWN];         // DCN conv output (pre-LN)
__device__ uint32_t g_wT_h[GN*KKN*2048];       // w_dcn fp16 fragment-baked (m16n8k16)
__device__ uint32_t g_wA_h[8*KKN*2048];        // w_off fp16 fragment-baked
__device__ uint4    g_xH  [BN*GN*8*HWN];       // x fp16 8-ch interleave: [b][g][c8][px]

// ---------------------------------------------------------------------------
// helpers
// ---------------------------------------------------------------------------
__device__ __forceinline__ void mma_f16(float* d, uint32_t a0, uint32_t a1,
                                        uint32_t a2, uint32_t a3,
                                        uint32_t b0, uint32_t b1) {
    asm volatile(
        "mma.sync.aligned.m16n8k16.row.col.f32.f16.f16.f32 "
        "{%0,%1,%2,%3}, {%4,%5,%6,%7}, {%8,%9}, {%0,%1,%2,%3};"
        : "+f"(d[0]), "+f"(d[1]), "+f"(d[2]), "+f"(d[3])
        : "r"(a0), "r"(a1), "r"(a2), "r"(a3), "r"(b0), "r"(b1));
}
__device__ __forceinline__ uint32_t pack_h2(float a, float b) {
    __half2 h = __floats2half2_rn(a, b);      // .x (low) = a
    return *reinterpret_cast<uint32_t*>(&h);
}
__device__ __forceinline__ __half2 u2h(uint32_t u) {
    return *reinterpret_cast<__half2*>(&u);
}
__device__ __forceinline__ uint32_t h2u(__half2 h) {
    return *reinterpret_cast<uint32_t*>(&h);
}

// ---------------------------------------------------------------------------
// Kernel 0a: w_dcn -> g_wT_h fp16 fragment-baked (m16n8k16).
// ---------------------------------------------------------------------------
__global__ void __launch_bounds__(256) prep_wT_k(const float* __restrict__ w_dcn)
{
    int i = blockIdx.x * 256 + threadIdx.x;
    if (i >= GN*KKN*2048) return;
    int tile = i >> 11;
    int j    = i & 2047;
    int r    = j & 3;
    int lane = (j >> 2) & 31;
    int fs   = j >> 7;                 // 0..15 = mt*4 + step
    int mt   = fs >> 2, step = fs & 3;
    int k    = tile % 9;
    int g    = tile / 9;
    int oc   = mt*16 + ((r & 1) << 3) + (lane >> 2);
    int c0   = step*16 + ((lane & 3) << 1) + ((r >> 1) << 3);
    float w0 = w_dcn[((g*CG + oc)*CG + c0    )*KKN + k];
    float w1 = w_dcn[((g*CG + oc)*CG + c0 + 1)*KKN + k];
    g_wT_h[i] = pack_h2(w0, w1);
}

// ---------------------------------------------------------------------------
// Kernel 0b: w_off -> g_wA_h fp16 fragment-baked.
// ---------------------------------------------------------------------------
__global__ void __launch_bounds__(256) prep_wA_k(const float* __restrict__ w_off)
{
    int i = blockIdx.x * 256 + threadIdx.x;
    if (i >= 8*KKN*2048) return;
    int tile = i >> 11;
    int j    = i & 2047;
    int r    = j & 3;
    int lane = (j >> 2) & 31;
    int fs   = j >> 7;                 // 0..15 = mt*2 + step
    int mt   = fs >> 1, step = fs & 1;
    int kk   = tile % 9;
    int cc   = tile / 9;
    int oc   = mt*16 + ((r & 1) << 3) + (lane >> 2);
    int c0   = step*16 + ((lane & 3) << 1) + ((r >> 1) << 3);
    float w0 = 0.f, w1 = 0.f;
    if (oc < OCF) {
        w0 = w_off[(oc*CN + cc*32 + c0    )*KKN + kk];
        w1 = w_off[(oc*CN + cc*32 + c0 + 1)*KKN + kk];
    }
    g_wA_h[i] = pack_h2(w0, w1);
}

// ---------------------------------------------------------------------------
// Kernel 0c: build g_xH[b][g][c8][px] (8 fp16 channels per uint4).
// ---------------------------------------------------------------------------
__global__ void __launch_bounds__(256) build_xH_k(const float* __restrict__ x)
{
    const int bg = blockIdx.z;
    const int c8 = blockIdx.y;
    const int px = blockIdx.x * 256 + threadIdx.x;
    const float* src = x + (size_t)bg*CG*HWN + c8*8*HWN + px;
    uint4 o;
    o.x = pack_h2(src[0],     src[HWN]);
    o.y = pack_h2(src[2*HWN], src[3*HWN]);
    o.z = pack_h2(src[4*HWN], src[5*HWN]);
    o.w = pack_h2(src[6*HWN], src[7*HWN]);
    g_xH[(size_t)(bg*8 + c8)*HWN + px] = o;
}

// ---------------------------------------------------------------------------
// Kernel 1: offset/mask conv, fp16 m16n8k16 (round-15 proven shape).
// grid (HN/2, BN), block 256: mg = wid&3, ng = wid>>2. 64 acc/thread.
// Patch: 4 rows x 16 crow x 72 half2; zeroed once.
// ---------------------------------------------------------------------------
#define OFC_BYTES (4*16*72*4)

__global__ void __launch_bounds__(256, 2) offset_conv_mma_k(
    const float* __restrict__ x, const float* __restrict__ b_off)
{
    extern __shared__ char smc[];
    uint32_t* patch_u = (uint32_t*)smc;          // half2 units
    const uint32_t* PH = (const uint32_t*)smc;

    const int h0  = blockIdx.x * 2;
    const int b   = blockIdx.y;
    const int t   = threadIdx.x;
    const int wid = t >> 5;
    const int lane = t & 31;
    const int lm4 = lane & 3;
    const int ld4 = lane >> 2;
    const int mg  = wid & 3;
    const int ng  = wid >> 2;

    float D[2][8][4];
#pragma unroll
    for (int s = 0; s < 2; s++)
#pragma unroll
        for (int n = 0; n < 8; n++)
#pragma unroll
            for (int i = 0; i < 4; i++) D[s][n][i] = 0.f;

#pragma unroll
    for (int i = t; i < 4*16*72; i += 256) patch_u[i] = 0u;

    const int colT = t & 63;
    const int p0   = t >> 6;

    for (int cc = 0; cc < 8; cc++) {
        __syncthreads();
        {
            const float* xb = x + ((b*CN + cc*32)*HN)*WN + colT;
#pragma unroll
            for (int p = p0; p < 64; p += 4) {
                int crow = p & 15;
                int r    = p >> 4;
                int y    = h0 - 1 + r;
                float v0 = 0.f, v1 = 0.f;
                if ((unsigned)y < HN) {
                    const float* xp = xb + (2*crow*HN + y)*WN;
                    v0 = xp[0];
                    v1 = xp[HWN];
                }
                patch_u[(r*16 + crow)*72 + colT + 1] = pack_h2(v0, v1);
            }
        }
        __syncthreads();

        for (int kk = 0; kk < KKN; kk++) {
            const uint4* wf = (const uint4*)(g_wA_h + (cc*9 + kk)*2048);
            const int ky = kk / 3, kx = kk - (kk/3)*3;
#pragma unroll
            for (int st = 0; st < 2; st++) {
                uint4 af0 = wf[((mg*2 + 0)*2 + st)*32 + lane];
                uint4 af1 = wf[((mg*2 + 1)*2 + st)*32 + lane];
                const int bb = ((ng + ky)*16 + st*8 + lm4)*72 + kx + ld4;
#pragma unroll
                for (int nt = 0; nt < 8; nt++) {
                    uint32_t b0 = PH[bb + nt*8];
                    uint32_t b1 = PH[bb + 4*72 + nt*8];
                    mma_f16(D[0][nt], af0.x, af0.y, af0.z, af0.w, b0, b1);
                    mma_f16(D[1][nt], af1.x, af1.y, af1.z, af1.w, b0, b1);
                }
            }
        }
    }

    const int h = h0 + ng;
#pragma unroll
    for (int s = 0; s < 2; s++) {
#pragma unroll
        for (int nt = 0; nt < 8; nt++) {
            int ocA = mg*32 + s*16 + ld4;
            int ocB = ocA + 8;
            int w   = nt*8 + lm4*2;
            if (ocA < OCF) {
                float bo = b_off[ocA];
                *reinterpret_cast<float2*>(&g_off[((b*OCF + ocA)*HN + h)*WN + w])
                    = make_float2(D[s][nt][0] + bo, D[s][nt][1] + bo);
            }
            if (ocB < OCF) {
                float bo = b_off[ocB];
                *reinterpret_cast<float2*>(&g_off[((b*OCF + ocB)*HN + h)*WN + w])
                    = make_float2(D[s][nt][2] + bo, D[s][nt][3] + bo);
            }
        }
    }
}

// ---------------------------------------------------------------------------
// Kernel 2: deformable sampling + grouped conv, fp16 m16n8k16
// (round-15 shape, warp tile 64oc x 32px) + DOUBLE-BUFFERED S:
// gather k writes S[k&1] while mma of k-1 read S[(k-1)&1] -> one barrier/k.
// grid (HN/4, GN, BN), block 256: ng = wid (px chunk ng*32).
// ---------------------------------------------------------------------------
#define DCN_PITCH  264
#define DCN_BUF    (32*DCN_PITCH)
#define DCN_BYTES  (2*DCN_BUF*4)

__global__ void __launch_bounds__(256, 2) dcn_mma_k(
    const float* __restrict__ b_dcn)
{
    extern __shared__ char smc[];
    uint32_t* SHbase = (uint32_t*)smc;    // half2 units, 2 buffers

    const int h0 = blockIdx.x * 4;
    const int g  = blockIdx.y;
    const int b  = blockIdx.z;
    const int t  = threadIdx.x;
    const int wid = t >> 5;
    const int lane = t & 31;
    const int lm4 = lane & 3;
    const int ld4 = lane >> 2;
    const int ng  = wid;              // px chunk: ng*32

    const int pxA = t;
    const int hA  = h0 + (t >> 6);
    const int wA  = t & 63;
    const uint4* xh = g_xH + (size_t)(b*GN + g)*8*HWN;

    float D[4][4][4];
#pragma unroll
    for (int s = 0; s < 4; s++)
#pragma unroll
        for (int n = 0; n < 4; n++)
#pragma unroll
            for (int i = 0; i < 4; i++) D[s][n][i] = 0.f;

    for (int k = 0; k < KKN; k++) {
        uint32_t* SH = SHbase + (k & 1)*DCN_BUF;
        // ---- bilinear corner data (registers) ----
        int i0, i1, i2, i3;
        __half2 w0h, w1h, w2h, w3h;
        {
            int ky = k / 3 - 1;
            int kx = k - (k/3)*3 - 1;
            int sp = hA*WN + wA;
            const float* ob = g_off + b*OCF*HWN;
            float oy = ob[((g*KKN + k)*2    )*HWN + sp];
            float ox = ob[((g*KKN + k)*2 + 1)*HWN + sp];
            float mz = ob[(2*GN*KKN + g*KKN + k)*HWN + sp];
            float mk = 1.f / (1.f + expf(-mz));
            float py  = (float)(hA + ky) + oy;
            float pxx = (float)(wA + kx) + ox;
            float y0f = floorf(py),  x0f = floorf(pxx);
            float wy1 = py - y0f,    wx1 = pxx - x0f;
            float wy0 = 1.f - wy1,   wx0 = 1.f - wx1;
            int y0 = (int)y0f, x0i = (int)x0f;
            int y1 = y0 + 1,   x1i = x0i + 1;
            bool vy0 = (y0 >= 0) & (y0 < HN);
            bool vy1 = (y1 >= 0) & (y1 < HN);
            bool vx0 = (x0i >= 0) & (x0i < WN);
            bool vx1 = (x1i >= 0) & (x1i < WN);
            int y0c = min(max(y0, 0), HN-1), y1c = min(max(y1, 0), HN-1);
            int x0c = min(max(x0i,0), WN-1), x1c = min(max(x1i,0), WN-1);
            i0 = y0c*WN + x0c;  i1 = y0c*WN + x1c;
            i2 = y1c*WN + x0c;  i3 = y1c*WN + x1c;
            w0h = __float2half2_rn((vy0 && vx0) ? wy0*wx0*mk : 0.f);
            w1h = __float2half2_rn((vy0 && vx1) ? wy0*wx1*mk : 0.f);
            w2h = __float2half2_rn((vy1 && vx0) ? wy1*wx0*mk : 0.f);
            w3h = __float2half2_rn((vy1 && vx1) ? wy1*wx1*mk : 0.f);
        }
        // ---- gather into buffer k&1 (no pre-barrier needed) ----
#pragma unroll 2
        for (int c8 = 0; c8 < 8; c8++) {
            const uint4* pl = xh + (size_t)c8*HWN;
            uint4 A = pl[i0], Bv = pl[i1], Cv = pl[i2], Dv = pl[i3];
            uint32_t* srow = SH + (4*c8)*DCN_PITCH + pxA;
            __half2 r;
            r = __hmul2(u2h(A.x), w0h);
            r = __hfma2(u2h(Bv.x), w1h, r);
            r = __hfma2(u2h(Cv.x), w2h, r);
            r = __hfma2(u2h(Dv.x), w3h, r);
            srow[0] = h2u(r);
            r = __hmul2(u2h(A.y), w0h);
            r = __hfma2(u2h(Bv.y), w1h, r);
            r = __hfma2(u2h(Cv.y), w2h, r);
            r = __hfma2(u2h(Dv.y), w3h, r);
            srow[DCN_PITCH] = h2u(r);
            r = __hmul2(u2h(A.z), w0h);
            r = __hfma2(u2h(Bv.z), w1h, r);
            r = __hfma2(u2h(Cv.z), w2h, r);
            r = __hfma2(u2h(Dv.z), w3h, r);
            srow[2*DCN_PITCH] = h2u(r);
            r = __hmul2(u2h(A.w), w0h);
            r = __hfma2(u2h(Bv.w), w1h, r);
            r = __hfma2(u2h(Cv.w), w2h, r);
            r = __hfma2(u2h(Dv.w), w3h, r);
            srow[3*DCN_PITCH] = h2u(r);
        }
        __syncthreads();

        // ---- mma: K=64 -> 4 k16-steps; A frags LDG.128, B frags LDS.32 ----
        const uint4* wf = (const uint4*)(g_wT_h + (g*KKN + k)*2048);
        const int nb = ng*32 + ld4;
#pragma unroll
        for (int st = 0; st < 4; st++) {
            uint4 af[4];
#pragma unroll
            for (int s = 0; s < 4; s++)
                af[s] = wf[((s*4 + st))*32 + lane];
            const int bb = (st*8 + lm4)*DCN_PITCH + nb;
#pragma unroll
            for (int nt = 0; nt < 4; nt++) {
                uint32_t b0 = SH[bb + nt*8];
                uint32_t b1 = SH[bb + 4*DCN_PITCH + nt*8];
#pragma unroll
                for (int s = 0; s < 4; s++)
                    mma_f16(D[s][nt], af[s].x, af[s].y, af[s].z, af[s].w, b0, b1);
            }
        }
        // no trailing barrier: next k gathers into the other buffer;
        // next k's own barrier orders its gather before its mma, and two
        // iterations apart the barrier chain protects buffer reuse.
    }

    // ---- epilogue: +bias, store ----
    const int h = h0 + (ng >> 1);
#pragma unroll
    for (int s = 0; s < 4; s++) {
#pragma unroll
        for (int nt = 0; nt < 4; nt++) {
            int ocA = g*CG + s*16 + ld4;
            int ocB = ocA + 8;
            int w   = (ng & 1)*32 + nt*8 + lm4*2;
            float boA = b_dcn[ocA], boB = b_dcn[ocB];
            *reinterpret_cast<float2*>(&g_out[((b*CN + ocA)*HN + h)*WN + w])
                = make_float2(D[s][nt][0] + boA, D[s][nt][1] + boA);
            *reinterpret_cast<float2*>(&g_out[((b*CN + ocB)*HN + h)*WN + w])
                = make_float2(D[s][nt][2] + boB, D[s][nt][3] + boB);
        }
    }
}

// ---------------------------------------------------------------------------
// Kernel 3: LayerNorm over C + sigmoid + gate — float4 I/O, register values.
// grid (HN, BN), block 256. Thread: 4-px quad (q=t&15) x 16 ch (cp=t>>4).
// ---------------------------------------------------------------------------
__global__ void __launch_bounds__(256) ln_gate_k(
    const float* __restrict__ x, const float* __restrict__ gamma,
    const float* __restrict__ beta, float* __restrict__ out)
{
    __shared__ float4 ssum[16][16];   // [cp][q]
    __shared__ float4 ssq [16][16];
    __shared__ float  smu[64], srinv[64];
    __shared__ float  sg[CN], sb[CN];

    const int b = blockIdx.y;
    const int h = blockIdx.x;
    const int t = threadIdx.x;
    const int q  = t & 15;
    const int cp = t >> 4;
    const int base = b*CN*HWN + h*WN;

    if (t < CN) { sg[t] = gamma[t]; sb[t] = beta[t]; }

    const float4* src = (const float4*)(g_out + base);
    float4 v[16];
    float4 s  = make_float4(0.f, 0.f, 0.f, 0.f);
    float4 qq = make_float4(0.f, 0.f, 0.f, 0.f);
#pragma unroll
    for (int j = 0; j < 16; j++) {
        float4 vv = src[(cp*16 + j)*(HWN/4) + q];
        v[j] = vv;
        s.x += vv.x; s.y += vv.y; s.z += vv.z; s.w += vv.w;
        qq.x += vv.x*vv.x; qq.y += vv.y*vv.y; qq.z += vv.z*vv.z; qq.w += vv.w*vv.w;
    }
    ssum[cp][q] = s; ssq[cp][q] = qq;
    __syncthreads();
    if (t < 64) {
        int pq = t >> 2, cm = t & 3;
        float ss = 0.f, sq = 0.f;
#pragma unroll
        for (int c2 = 0; c2 < 16; c2++) {
            ss += (&ssum[c2][pq].x)[cm];
            sq += (&ssq [c2][pq].x)[cm];
        }
        float mu  = ss * (1.f/CN);
        float var = fmaxf(sq * (1.f/CN) - mu*mu, 0.f);
        smu[t]   = mu;
        srinv[t] = rsqrtf(var + 1e-5f);
    }
    __syncthreads();

    const float4 mu4 = *reinterpret_cast<const float4*>(&smu[q*4]);
    const float4 ri4 = *reinterpret_cast<const float4*>(&srinv[q*4]);
    const float4* xs = (const float4*)(x + base);
    float4* os = (float4*)(out + base);
#pragma unroll
    for (int j = 0; j < 16; j++) {
        int c = cp*16 + j;
        float gm = sg[c], bt = sb[c];
        float4 xv = xs[c*(HWN/4) + q];
        float4 o;
        float z;
        z = (v[j].x - mu4.x) * ri4.x * gm + bt; o.x = xv.x / (1.f + expf(-z));
        z = (v[j].y - mu4.y) * ri4.y * gm + bt; o.y = xv.y / (1.f + expf(-z));
        z = (v[j].z - mu4.z) * ri4.z * gm + bt; o.z = xv.z / (1.f + expf(-z));
        z = (v[j].w - mu4.w) * ri4.w * gm + bt; o.w = xv.w / (1.f + expf(-z));
        os[c*(HWN/4) + q] = o;
    }
}

// ---------------------------------------------------------------------------
// Entry point
// ---------------------------------------------------------------------------
extern "C" void kernel_launch(void* const* d_in, const int* in_sizes, int n_in,
                              void* d_out, int out_size)
{
    const float* x     = (const float*)d_in[0];
    const float* w_off = (const float*)d_in[1];
    const float* b_off = (const float*)d_in[2];
    const float* w_dcn = (const float*)d_in[3];
    const float* b_dcn = (const float*)d_in[4];
    const float* gamma = (const float*)d_in[5];
    const float* beta  = (const float*)d_in[6];
    float* out = (float*)d_out;

    (void)in_sizes; (void)n_in; (void)out_size;

    cudaFuncSetAttribute(offset_conv_mma_k, cudaFuncAttributeMaxDynamicSharedMemorySize,
                         OFC_BYTES);
    cudaFuncSetAttribute(dcn_mma_k, cudaFuncAttributeMaxDynamicSharedMemorySize,
                         DCN_BYTES);

    prep_wT_k<<<(GN*KKN*2048 + 255)/256, 256>>>(w_dcn);
    prep_wA_k<<<(8*KKN*2048 + 255)/256, 256>>>(w_off);
    build_xH_k<<<dim3(HWN/256, 8, BN*GN), 256>>>(x);
    offset_conv_mma_k<<<dim3(HN/2, BN), 256, OFC_BYTES>>>(x, b_off);
    dcn_mma_k<<<dim3(HN/4, GN, BN), 256, DCN_BYTES>>>(b_dcn);
    ln_gate_k<<<dim3(HN, BN), 256>>>(x, gamma, beta, out);
}